// round 3
// baseline (speedup 1.0000x reference)
#include <cuda_runtime.h>

#define N_NODES 50000
#define F       128
#define E_MAX   800000
#define NPB     32      // nodes per block in the fused kernel
#define KT      32      // weight k-tile

// ---- static device scratch (no allocs allowed) ----
__device__ int g_deg[N_NODES];
__device__ int g_off[N_NODES + 1];
__device__ int g_cursor[N_NODES];
__device__ int g_src_sorted[E_MAX];

// ---- packed fp32x2 helpers (sm_100+; ptxas never auto-emits FFMA2) ----
#define FMA2(d, a, b) asm("fma.rn.f32x2 %0, %1, %2, %0;" : "+l"(d) : "l"(a), "l"(b))
#define PACK2(d, s)   asm("mov.b64 %0, {%1, %1};" : "=l"(d) : "f"(s))
#define UNPACK2(lo, hi, v) asm("mov.b64 {%0, %1}, %2;" : "=f"(lo), "=f"(hi) : "l"(v))

// ---------------------------------------------------------------------------
// CSR build: zero degrees -> histogram -> prefix scan -> reorder src by dst
// ---------------------------------------------------------------------------
__global__ void zero_deg_kernel() {
    int i = blockIdx.x * blockDim.x + threadIdx.x;
    if (i < N_NODES) g_deg[i] = 0;
}

__global__ void hist_kernel(const int* __restrict__ dst, int E) {
    int e = blockIdx.x * blockDim.x + threadIdx.x;
    if (e < E) atomicAdd(&g_deg[dst[e]], 1);
}

// single-block hierarchical exclusive scan over 50k degrees
__global__ void __launch_bounds__(1024) scan_kernel() {
    __shared__ int wsum[32];
    __shared__ int carry;
    const int t = threadIdx.x, lane = t & 31, wid = t >> 5;
    if (t == 0) carry = 0;
    __syncthreads();
    for (int base = 0; base < N_NODES; base += 1024) {
        int i = base + t;
        int v = (i < N_NODES) ? g_deg[i] : 0;
        int inc = v;
#pragma unroll
        for (int d = 1; d < 32; d <<= 1) {
            int n = __shfl_up_sync(0xffffffffu, inc, d);
            if (lane >= d) inc += n;
        }
        if (lane == 31) wsum[wid] = inc;
        __syncthreads();
        if (wid == 0) {
            int ws = wsum[lane];
            int wi = ws;
#pragma unroll
            for (int d = 1; d < 32; d <<= 1) {
                int n = __shfl_up_sync(0xffffffffu, wi, d);
                if (lane >= d) wi += n;
            }
            wsum[lane] = wi - ws;   // exclusive warp offsets
        }
        __syncthreads();
        int excl = carry + wsum[wid] + (inc - v);
        if (i < N_NODES) { g_off[i] = excl; g_cursor[i] = excl; }
        __syncthreads();            // all reads of carry done
        if (t == 1023) carry = excl + v;
        __syncthreads();            // carry visible for next iter
    }
    if (t == 0) g_off[N_NODES] = carry;
}

__global__ void reorder_kernel(const int* __restrict__ src,
                               const int* __restrict__ dst, int E) {
    int e = blockIdx.x * blockDim.x + threadIdx.x;
    if (e < E) {
        int d = dst[e];
        int pos = atomicAdd(&g_cursor[d], 1);
        g_src_sorted[pos] = src[e];
    }
}

// ---------------------------------------------------------------------------
// Fused kernel: gather-aggregate neighbors into smem, then dual GEMM + bias +
// ReLU with packed fp32x2 FMAs. 256 threads, 32 nodes per block.
// ---------------------------------------------------------------------------
struct SmemLayout {
    float sAgg[NPB][132];
    float sX[NPB][132];
    float sWrel[KT][132];
    float sWroot[KT][132];
};

__global__ void __launch_bounds__(256)
fused_kernel(const float4* __restrict__ x4,
             const float* __restrict__ Wrel,
             const float* __restrict__ brel,
             const float* __restrict__ Wroot,
             float* __restrict__ out) {
    extern __shared__ char smem_raw[];
    SmemLayout& sm = *reinterpret_cast<SmemLayout*>(smem_raw);

    const int t    = threadIdx.x;
    const int warp = t >> 5;
    const int lane = t & 31;
    const int nodeBase = blockIdx.x * NPB;

    // ---- Phase A: per-node neighbor gather-sum (CSR) + stage x row ----
#pragma unroll
    for (int q = 0; q < 4; q++) {
        int slot = warp * 4 + q;
        int node = nodeBase + slot;
        float4 acc = make_float4(0.f, 0.f, 0.f, 0.f);
        float4 xv  = make_float4(0.f, 0.f, 0.f, 0.f);
        if (node < N_NODES) {
            xv = x4[node * 32 + lane];
            int beg = g_off[node];
            int end = g_off[node + 1];
            for (int i = beg; i < end; i++) {
                int s = g_src_sorted[i];          // broadcast load
                float4 v = x4[s * 32 + lane];     // 512B/warp L2 gather
                acc.x += v.x; acc.y += v.y; acc.z += v.z; acc.w += v.w;
            }
        }
        *reinterpret_cast<float4*>(&sm.sAgg[slot][lane * 4]) = acc;
        *reinterpret_cast<float4*>(&sm.sX[slot][lane * 4])   = xv;
    }

    // ---- Phase B: dual GEMM, 2 nodes x 8 outputs per thread, f32x2 FMAs ----
    const int og = t & 15;     // output cols og*8 .. og*8+7
    const int ng = t >> 4;     // nodes ng*2, ng*2+1

    unsigned long long acc[2][4];
#pragma unroll
    for (int n = 0; n < 2; n++)
#pragma unroll
        for (int p = 0; p < 4; p++) acc[n][p] = 0ull;   // packed (0.f, 0.f)

    for (int kc = 0; kc < F; kc += KT) {
        __syncthreads();    // prior tile fully consumed (covers Phase A too)
        // stage weights transposed: sW[kk][o] = W[o][kc+kk]
#pragma unroll
        for (int i = 0; i < (128 * KT) / 256; i++) {
            int idx = t + i * 256;
            int o  = idx >> 5;
            int kk = idx & 31;
            sm.sWrel[kk][o]  = Wrel [o * F + kc + kk];
            sm.sWroot[kk][o] = Wroot[o * F + kc + kk];
        }
        __syncthreads();

#pragma unroll
        for (int kk = 0; kk < KT; kk++) {
            // 8 consecutive weight cols = 4 packed pairs per matrix
            ulonglong2 wr0 = *reinterpret_cast<const ulonglong2*>(&sm.sWrel[kk][og * 8]);
            ulonglong2 wr1 = *reinterpret_cast<const ulonglong2*>(&sm.sWrel[kk][og * 8 + 4]);
            ulonglong2 wo0 = *reinterpret_cast<const ulonglong2*>(&sm.sWroot[kk][og * 8]);
            ulonglong2 wo1 = *reinterpret_cast<const ulonglong2*>(&sm.sWroot[kk][og * 8 + 4]);
#pragma unroll
            for (int n = 0; n < 2; n++) {
                float a  = sm.sAgg[ng * 2 + n][kc + kk];
                float xx = sm.sX[ng * 2 + n][kc + kk];
                unsigned long long a2, x2;
                PACK2(a2, a);
                PACK2(x2, xx);
                FMA2(acc[n][0], a2, wr0.x);
                FMA2(acc[n][1], a2, wr0.y);
                FMA2(acc[n][2], a2, wr1.x);
                FMA2(acc[n][3], a2, wr1.y);
                FMA2(acc[n][0], x2, wo0.x);
                FMA2(acc[n][1], x2, wo0.y);
                FMA2(acc[n][2], x2, wo1.x);
                FMA2(acc[n][3], x2, wo1.y);
            }
        }
    }

    // ---- epilogue: bias + relu + store ----
    float4 b0 = *reinterpret_cast<const float4*>(&brel[og * 8]);
    float4 b1 = *reinterpret_cast<const float4*>(&brel[og * 8 + 4]);
#pragma unroll
    for (int n = 0; n < 2; n++) {
        int node = nodeBase + ng * 2 + n;
        if (node < N_NODES) {
            float r[8];
            UNPACK2(r[0], r[1], acc[n][0]);
            UNPACK2(r[2], r[3], acc[n][1]);
            UNPACK2(r[4], r[5], acc[n][2]);
            UNPACK2(r[6], r[7], acc[n][3]);
            float4 o0, o1;
            o0.x = fmaxf(r[0] + b0.x, 0.f);
            o0.y = fmaxf(r[1] + b0.y, 0.f);
            o0.z = fmaxf(r[2] + b0.z, 0.f);
            o0.w = fmaxf(r[3] + b0.w, 0.f);
            o1.x = fmaxf(r[4] + b1.x, 0.f);
            o1.y = fmaxf(r[5] + b1.y, 0.f);
            o1.z = fmaxf(r[6] + b1.z, 0.f);
            o1.w = fmaxf(r[7] + b1.w, 0.f);
            float4* orow = reinterpret_cast<float4*>(out) + node * 32;
            orow[og * 2]     = o0;
            orow[og * 2 + 1] = o1;
        }
    }
}

// ---------------------------------------------------------------------------
extern "C" void kernel_launch(void* const* d_in, const int* in_sizes, int n_in,
                              void* d_out, int out_size) {
    const float* x     = (const float*)d_in[0];
    const int*   ei    = (const int*)d_in[1];     // int32 (JAX x64 disabled)
    const float* Wrel  = (const float*)d_in[2];
    const float* brel  = (const float*)d_in[3];
    const float* Wroot = (const float*)d_in[4];
    float*       out   = (float*)d_out;

    const int E = in_sizes[1] / 2;                // 800000
    const int* src = ei;
    const int* dst = ei + E;

    const int smem_bytes = (int)sizeof(SmemLayout);   // ~67.6 KB
    static bool attr_set = false;
    if (!attr_set) {
        cudaFuncSetAttribute(fused_kernel,
                             cudaFuncAttributeMaxDynamicSharedMemorySize,
                             smem_bytes);
        attr_set = true;
    }

    // 1) CSR build
    zero_deg_kernel<<<(N_NODES + 255) / 256, 256>>>();
    hist_kernel<<<(E + 255) / 256, 256>>>(dst, E);
    scan_kernel<<<1, 1024>>>();
    reorder_kernel<<<(E + 255) / 256, 256>>>(src, dst, E);

    // 2) fused gather + dual GEMM + bias + relu
    int blocks = (N_NODES + NPB - 1) / NPB;
    fused_kernel<<<blocks, 256, smem_bytes>>>(
        reinterpret_cast<const float4*>(x), Wrel, brel, Wroot, out);
}

// round 4
// speedup vs baseline: 1.2455x; 1.2455x over previous
#include <cuda_runtime.h>

#define N_NODES 50000
#define F       128
#define E_MAX   800000
#define NPB     64      // nodes per block in GEMM
#define KT      32      // weight k-tile

// ---- static device scratch (no allocs allowed) ----
__device__ int   g_deg[N_NODES];
__device__ int   g_off[N_NODES + 1];
__device__ int   g_cursor[N_NODES];
__device__ int   g_src_sorted[E_MAX];
__device__ float g_agg[N_NODES * F];

// ---- packed fp32x2 helpers (sm_100+; ptxas never auto-emits FFMA2) ----
#define FMA2(d, a, b) asm("fma.rn.f32x2 %0, %1, %2, %0;" : "+l"(d) : "l"(a), "l"(b))
#define UNPACK2(lo, hi, v) asm("mov.b64 {%0, %1}, %2;" : "=f"(lo), "=f"(hi) : "l"(v))

// ---------------------------------------------------------------------------
// CSR build: zero degrees -> histogram -> prefix scan -> reorder src by dst
// ---------------------------------------------------------------------------
__global__ void zero_deg_kernel() {
    int i = blockIdx.x * blockDim.x + threadIdx.x;
    if (i < N_NODES) g_deg[i] = 0;
}

__global__ void hist_kernel(const int* __restrict__ dst, int E) {
    int e = blockIdx.x * blockDim.x + threadIdx.x;
    if (e < E) atomicAdd(&g_deg[dst[e]], 1);
}

// single-block hierarchical exclusive scan over 50k degrees
__global__ void __launch_bounds__(1024) scan_kernel() {
    __shared__ int wsum[32];
    __shared__ int carry;
    const int t = threadIdx.x, lane = t & 31, wid = t >> 5;
    if (t == 0) carry = 0;
    __syncthreads();
    for (int base = 0; base < N_NODES; base += 1024) {
        int i = base + t;
        int v = (i < N_NODES) ? g_deg[i] : 0;
        int inc = v;
#pragma unroll
        for (int d = 1; d < 32; d <<= 1) {
            int n = __shfl_up_sync(0xffffffffu, inc, d);
            if (lane >= d) inc += n;
        }
        if (lane == 31) wsum[wid] = inc;
        __syncthreads();
        if (wid == 0) {
            int ws = wsum[lane];
            int wi = ws;
#pragma unroll
            for (int d = 1; d < 32; d <<= 1) {
                int n = __shfl_up_sync(0xffffffffu, wi, d);
                if (lane >= d) wi += n;
            }
            wsum[lane] = wi - ws;   // exclusive warp offsets
        }
        __syncthreads();
        int excl = carry + wsum[wid] + (inc - v);
        if (i < N_NODES) { g_off[i] = excl; g_cursor[i] = excl; }
        __syncthreads();
        if (t == 1023) carry = excl + v;
        __syncthreads();
    }
    if (t == 0) g_off[N_NODES] = carry;
}

__global__ void reorder_kernel(const int* __restrict__ src,
                               const int* __restrict__ dst, int E) {
    int e = blockIdx.x * blockDim.x + threadIdx.x;
    if (e < E) {
        int d = dst[e];
        int pos = atomicAdd(&g_cursor[d], 1);
        g_src_sorted[pos] = src[e];
    }
}

// ---------------------------------------------------------------------------
// Aggregate: one warp per node, neighbor loop unrolled x4 for MLP.
// 50k warps chip-wide; pure L2-bandwidth-bound gather-sum.
// ---------------------------------------------------------------------------
__global__ void __launch_bounds__(256)
agg_kernel(const float4* __restrict__ x4) {
    int node = (blockIdx.x * blockDim.x + threadIdx.x) >> 5;
    int lane = threadIdx.x & 31;
    if (node >= N_NODES) return;

    int beg = g_off[node];
    int end = g_off[node + 1];
    float4 acc = make_float4(0.f, 0.f, 0.f, 0.f);

    int i = beg;
    for (; i + 4 <= end; i += 4) {
        int s0 = g_src_sorted[i];
        int s1 = g_src_sorted[i + 1];
        int s2 = g_src_sorted[i + 2];
        int s3 = g_src_sorted[i + 3];
        float4 v0 = x4[s0 * 32 + lane];
        float4 v1 = x4[s1 * 32 + lane];
        float4 v2 = x4[s2 * 32 + lane];
        float4 v3 = x4[s3 * 32 + lane];
        acc.x += (v0.x + v1.x) + (v2.x + v3.x);
        acc.y += (v0.y + v1.y) + (v2.y + v3.y);
        acc.z += (v0.z + v1.z) + (v2.z + v3.z);
        acc.w += (v0.w + v1.w) + (v2.w + v3.w);
    }
    for (; i < end; i++) {
        int s = g_src_sorted[i];
        float4 v = x4[s * 32 + lane];
        acc.x += v.x; acc.y += v.y; acc.z += v.z; acc.w += v.w;
    }
    reinterpret_cast<float4*>(g_agg)[node * 32 + lane] = acc;
}

// ---------------------------------------------------------------------------
// Dual GEMM + bias + ReLU with packed fp32x2 FMAs.
// 256 threads, 64 nodes/block. Thread = 4 nodes x 8 outputs (4 f32x2 accums).
// Inputs pre-duplicated {a,a} in smem so the FFMA2 scalar operand is one LDS.64.
// ---------------------------------------------------------------------------
struct GemmSmem {
    float2 sW2rel[KT][64];    // [kk][o/2] = (W[2op][k], W[2op+1][k])   16KB
    float2 sW2root[KT][64];   //                                        16KB
    float2 sA2[NPB][KT];      // [node][kk] = (a,a)                     16KB
    float2 sX2[NPB][KT];      //                                        16KB
};

__global__ void __launch_bounds__(256)
gemm_relu_kernel(const float* __restrict__ x,
                 const float* __restrict__ Wrel,
                 const float* __restrict__ brel,
                 const float* __restrict__ Wroot,
                 float* __restrict__ out) {
    extern __shared__ char smem_raw[];
    GemmSmem& sm = *reinterpret_cast<GemmSmem*>(smem_raw);

    const int t  = threadIdx.x;
    const int og = t & 15;     // output cols og*8 .. og*8+7
    const int ng = t >> 4;     // nodes ng*4 .. ng*4+3
    const int nodeBase = blockIdx.x * NPB;

    unsigned long long acc[4][4];
#pragma unroll
    for (int n = 0; n < 4; n++)
#pragma unroll
        for (int p = 0; p < 4; p++) acc[n][p] = 0ull;

    for (int kc = 0; kc < F; kc += KT) {
        __syncthreads();

        // --- stage weights as adjacent-output pairs: sW2[kk][o/2]
        {
            int o  = t >> 1;            // 0..127
            int kq = (t & 1) * 16;      // 0 or 16
#pragma unroll
            for (int j = 0; j < 4; j++) {
                float4 wr = *reinterpret_cast<const float4*>(&Wrel [o * F + kc + kq + j * 4]);
                float4 wo = *reinterpret_cast<const float4*>(&Wroot[o * F + kc + kq + j * 4]);
                const float* wrp = reinterpret_cast<const float*>(&wr);
                const float* wop = reinterpret_cast<const float*>(&wo);
#pragma unroll
                for (int c = 0; c < 4; c++) {
                    reinterpret_cast<float*>(&sm.sW2rel [kq + j * 4 + c][o >> 1])[o & 1] = wrp[c];
                    reinterpret_cast<float*>(&sm.sW2root[kq + j * 4 + c][o >> 1])[o & 1] = wop[c];
                }
            }
        }
        // --- stage inputs duplicated: sA2[node][kk] = {a,a}
        {
            int slot = t >> 2;          // 0..63
            int kq   = (t & 3) * 8;     // 0,8,16,24
            int node = nodeBase + slot;
            int gc   = node < N_NODES ? node : N_NODES - 1;
#pragma unroll
            for (int j = 0; j < 2; j++) {
                float4 a  = *reinterpret_cast<const float4*>(&g_agg[gc * F + kc + kq + j * 4]);
                float4 xx = *reinterpret_cast<const float4*>(&x    [gc * F + kc + kq + j * 4]);
                const float* ap = reinterpret_cast<const float*>(&a);
                const float* xp = reinterpret_cast<const float*>(&xx);
#pragma unroll
                for (int c = 0; c < 4; c++) {
                    sm.sA2[slot][kq + j * 4 + c] = make_float2(ap[c], ap[c]);
                    sm.sX2[slot][kq + j * 4 + c] = make_float2(xp[c], xp[c]);
                }
            }
        }
        __syncthreads();

        // --- compute: per kk, 4 LDS.128 (weights) + 8 LDS.64 (inputs) + 32 FFMA2
        const int opb = og * 4;
#pragma unroll
        for (int kk = 0; kk < KT; kk++) {
            ulonglong2 wrA = *reinterpret_cast<const ulonglong2*>(&sm.sW2rel [kk][opb]);
            ulonglong2 wrB = *reinterpret_cast<const ulonglong2*>(&sm.sW2rel [kk][opb + 2]);
            ulonglong2 woA = *reinterpret_cast<const ulonglong2*>(&sm.sW2root[kk][opb]);
            ulonglong2 woB = *reinterpret_cast<const ulonglong2*>(&sm.sW2root[kk][opb + 2]);
#pragma unroll
            for (int n = 0; n < 4; n++) {
                unsigned long long a2 = *reinterpret_cast<const unsigned long long*>(&sm.sA2[ng * 4 + n][kk]);
                unsigned long long x2 = *reinterpret_cast<const unsigned long long*>(&sm.sX2[ng * 4 + n][kk]);
                FMA2(acc[n][0], a2, wrA.x);
                FMA2(acc[n][1], a2, wrA.y);
                FMA2(acc[n][2], a2, wrB.x);
                FMA2(acc[n][3], a2, wrB.y);
                FMA2(acc[n][0], x2, woA.x);
                FMA2(acc[n][1], x2, woA.y);
                FMA2(acc[n][2], x2, woB.x);
                FMA2(acc[n][3], x2, woB.y);
            }
        }
    }

    // ---- epilogue: bias + relu + store ----
    float4 b0 = *reinterpret_cast<const float4*>(&brel[og * 8]);
    float4 b1 = *reinterpret_cast<const float4*>(&brel[og * 8 + 4]);
#pragma unroll
    for (int n = 0; n < 4; n++) {
        int node = nodeBase + ng * 4 + n;
        if (node < N_NODES) {
            float r[8];
            UNPACK2(r[0], r[1], acc[n][0]);
            UNPACK2(r[2], r[3], acc[n][1]);
            UNPACK2(r[4], r[5], acc[n][2]);
            UNPACK2(r[6], r[7], acc[n][3]);
            float4 o0, o1;
            o0.x = fmaxf(r[0] + b0.x, 0.f);
            o0.y = fmaxf(r[1] + b0.y, 0.f);
            o0.z = fmaxf(r[2] + b0.z, 0.f);
            o0.w = fmaxf(r[3] + b0.w, 0.f);
            o1.x = fmaxf(r[4] + b1.x, 0.f);
            o1.y = fmaxf(r[5] + b1.y, 0.f);
            o1.z = fmaxf(r[6] + b1.z, 0.f);
            o1.w = fmaxf(r[7] + b1.w, 0.f);
            float4* orow = reinterpret_cast<float4*>(out) + node * 32;
            orow[og * 2]     = o0;
            orow[og * 2 + 1] = o1;
        }
    }
}

// ---------------------------------------------------------------------------
extern "C" void kernel_launch(void* const* d_in, const int* in_sizes, int n_in,
                              void* d_out, int out_size) {
    const float* x     = (const float*)d_in[0];
    const int*   ei    = (const int*)d_in[1];     // int32 (JAX x64 disabled)
    const float* Wrel  = (const float*)d_in[2];
    const float* brel  = (const float*)d_in[3];
    const float* Wroot = (const float*)d_in[4];
    float*       out   = (float*)d_out;

    const int E = in_sizes[1] / 2;                // 800000
    const int* src = ei;
    const int* dst = ei + E;

    const int smem_bytes = (int)sizeof(GemmSmem);     // 64KB
    static bool attr_set = false;
    if (!attr_set) {
        cudaFuncSetAttribute(gemm_relu_kernel,
                             cudaFuncAttributeMaxDynamicSharedMemorySize,
                             smem_bytes);
        attr_set = true;
    }

    // 1) CSR build
    zero_deg_kernel<<<(N_NODES + 255) / 256, 256>>>();
    hist_kernel<<<(E + 255) / 256, 256>>>(dst, E);
    scan_kernel<<<1, 1024>>>();
    reorder_kernel<<<(E + 255) / 256, 256>>>(src, dst, E);

    // 2) aggregate: warp per node (no zero pass needed; full overwrite)
    agg_kernel<<<(N_NODES * 32 + 255) / 256, 256>>>(
        reinterpret_cast<const float4*>(x));

    // 3) dual GEMM + bias + relu
    gemm_relu_kernel<<<(N_NODES + NPB - 1) / NPB, 256, smem_bytes>>>(
        x, Wrel, brel, Wroot, out);
}

// round 5
// speedup vs baseline: 1.6350x; 1.3127x over previous
#include <cuda_runtime.h>

#define N_NODES 50000
#define F       128
#define E_MAX   800000
#define NPB     128     // nodes per block in GEMM
#define KT      32      // weight k-tile

// ---- static device scratch (no allocs allowed) ----
__device__ int   g_deg[N_NODES];
__device__ int   g_off[N_NODES + 1];
__device__ int   g_cursor[N_NODES];
__device__ int   g_src_sorted[E_MAX];
__device__ float g_agg[N_NODES * F];

// ---- packed fp32x2 helpers (sm_100+; ptxas never auto-emits FFMA2) ----
#define FMA2(d, a, b) asm("fma.rn.f32x2 %0, %1, %2, %0;" : "+l"(d) : "l"(a), "l"(b))
#define UNPACK2(lo, hi, v) asm("mov.b64 {%0, %1}, %2;" : "=f"(lo), "=f"(hi) : "l"(v))

// ---------------------------------------------------------------------------
// CSR build: zero degrees -> histogram -> prefix scan -> reorder src by dst
// ---------------------------------------------------------------------------
__global__ void zero_deg_kernel() {
    int i = blockIdx.x * blockDim.x + threadIdx.x;
    if (i < N_NODES) g_deg[i] = 0;
}

__global__ void hist_kernel(const int* __restrict__ dst, int E) {
    int e = blockIdx.x * blockDim.x + threadIdx.x;
    if (e < E) atomicAdd(&g_deg[dst[e]], 1);
}

__global__ void __launch_bounds__(1024) scan_kernel() {
    __shared__ int wsum[32];
    __shared__ int carry;
    const int t = threadIdx.x, lane = t & 31, wid = t >> 5;
    if (t == 0) carry = 0;
    __syncthreads();
    for (int base = 0; base < N_NODES; base += 1024) {
        int i = base + t;
        int v = (i < N_NODES) ? g_deg[i] : 0;
        int inc = v;
#pragma unroll
        for (int d = 1; d < 32; d <<= 1) {
            int n = __shfl_up_sync(0xffffffffu, inc, d);
            if (lane >= d) inc += n;
        }
        if (lane == 31) wsum[wid] = inc;
        __syncthreads();
        if (wid == 0) {
            int ws = wsum[lane];
            int wi = ws;
#pragma unroll
            for (int d = 1; d < 32; d <<= 1) {
                int n = __shfl_up_sync(0xffffffffu, wi, d);
                if (lane >= d) wi += n;
            }
            wsum[lane] = wi - ws;
        }
        __syncthreads();
        int excl = carry + wsum[wid] + (inc - v);
        if (i < N_NODES) { g_off[i] = excl; g_cursor[i] = excl; }
        __syncthreads();
        if (t == 1023) carry = excl + v;
        __syncthreads();
    }
    if (t == 0) g_off[N_NODES] = carry;
}

__global__ void reorder_kernel(const int* __restrict__ src,
                               const int* __restrict__ dst, int E) {
    int e = blockIdx.x * blockDim.x + threadIdx.x;
    if (e < E) {
        int d = dst[e];
        int pos = atomicAdd(&g_cursor[d], 1);
        g_src_sorted[pos] = src[e];
    }
}

// ---------------------------------------------------------------------------
// Aggregate: one warp per node, neighbor loop unrolled x8 for MLP.
// ---------------------------------------------------------------------------
__global__ void __launch_bounds__(256)
agg_kernel(const float4* __restrict__ x4) {
    int node = (blockIdx.x * blockDim.x + threadIdx.x) >> 5;
    int lane = threadIdx.x & 31;
    if (node >= N_NODES) return;

    int beg = g_off[node];
    int end = g_off[node + 1];
    float4 acc = make_float4(0.f, 0.f, 0.f, 0.f);

    int i = beg;
    for (; i + 8 <= end; i += 8) {
        int s[8];
#pragma unroll
        for (int u = 0; u < 8; u++) s[u] = g_src_sorted[i + u];
        float4 v[8];
#pragma unroll
        for (int u = 0; u < 8; u++) v[u] = x4[s[u] * 32 + lane];
#pragma unroll
        for (int u = 0; u < 8; u++) {
            acc.x += v[u].x; acc.y += v[u].y;
            acc.z += v[u].z; acc.w += v[u].w;
        }
    }
    for (; i < end; i++) {
        int s = g_src_sorted[i];
        float4 v = x4[s * 32 + lane];
        acc.x += v.x; acc.y += v.y; acc.z += v.z; acc.w += v.w;
    }
    reinterpret_cast<float4*>(g_agg)[node * 32 + lane] = acc;
}

// ---------------------------------------------------------------------------
// Dual GEMM + bias + ReLU, FFMA2. 256 threads, 128 nodes/block.
// Thread tile: 8 outputs (og = t>>4, broadcast weights) x 8 nodes
// (ng = t&15, nodes ng+16n -> conflict-free padded smem rows).
// ---------------------------------------------------------------------------
struct GemmSmem {
    float2 sW2rel [KT][64];        // [kk][o/2] = (W[2p][k], W[2p+1][k])  16KB
    float2 sW2root[KT][64];        //                                     16KB
    float2 sA2[NPB][KT + 1];       // [node][kk] = (a,a), padded row      33.8KB
    float2 sX2[NPB][KT + 1];       //                                     33.8KB
};

__global__ void __launch_bounds__(256, 2)
gemm_relu_kernel(const float* __restrict__ x,
                 const float* __restrict__ Wrel,
                 const float* __restrict__ brel,
                 const float* __restrict__ Wroot,
                 float* __restrict__ out) {
    extern __shared__ char smem_raw[];
    GemmSmem& sm = *reinterpret_cast<GemmSmem*>(smem_raw);

    const int t  = threadIdx.x;
    const int og = t >> 4;     // 0..15 -> output cols og*8 .. og*8+7 (uniform/half-warp)
    const int ng = t & 15;     // nodes ng, ng+16, ..., ng+112
    const int nodeBase = blockIdx.x * NPB;

    unsigned long long acc[8][4];
#pragma unroll
    for (int n = 0; n < 8; n++)
#pragma unroll
        for (int p = 0; p < 4; p++) acc[n][p] = 0ull;

    for (int kc = 0; kc < F; kc += KT) {
        __syncthreads();

        // --- stage weights as adjacent-output pairs: sW2[kk][o/2]
        {
            int o  = t >> 1;            // 0..127
            int kq = (t & 1) * 16;      // 0 or 16
#pragma unroll
            for (int j = 0; j < 4; j++) {
                float4 wr = *reinterpret_cast<const float4*>(&Wrel [o * F + kc + kq + j * 4]);
                float4 wo = *reinterpret_cast<const float4*>(&Wroot[o * F + kc + kq + j * 4]);
                const float* wrp = reinterpret_cast<const float*>(&wr);
                const float* wop = reinterpret_cast<const float*>(&wo);
#pragma unroll
                for (int c = 0; c < 4; c++) {
                    reinterpret_cast<float*>(&sm.sW2rel [kq + j * 4 + c][o >> 1])[o & 1] = wrp[c];
                    reinterpret_cast<float*>(&sm.sW2root[kq + j * 4 + c][o >> 1])[o & 1] = wop[c];
                }
            }
        }
        // --- stage inputs duplicated: sA2[slot][kk] = {a,a}
        {
            int slot = t >> 1;          // 0..127
            int kq   = (t & 1) * 16;
            int node = nodeBase + slot;
            int gc   = node < N_NODES ? node : N_NODES - 1;
#pragma unroll
            for (int j = 0; j < 4; j++) {
                float4 a  = *reinterpret_cast<const float4*>(&g_agg[gc * F + kc + kq + j * 4]);
                float4 xx = *reinterpret_cast<const float4*>(&x    [gc * F + kc + kq + j * 4]);
                const float* ap = reinterpret_cast<const float*>(&a);
                const float* xp = reinterpret_cast<const float*>(&xx);
#pragma unroll
                for (int c = 0; c < 4; c++) {
                    sm.sA2[slot][kq + j * 4 + c] = make_float2(ap[c], ap[c]);
                    sm.sX2[slot][kq + j * 4 + c] = make_float2(xp[c], xp[c]);
                }
            }
        }
        __syncthreads();

        // --- compute: per kk: 4 broadcast LDS.128 (weights) + 16 cf LDS.64
        //     (inputs) + 64 FFMA2  -> FMA-pipe bound
        const int opb = og * 4;
#pragma unroll
        for (int kk = 0; kk < KT; kk++) {
            ulonglong2 wrA = *reinterpret_cast<const ulonglong2*>(&sm.sW2rel [kk][opb]);
            ulonglong2 wrB = *reinterpret_cast<const ulonglong2*>(&sm.sW2rel [kk][opb + 2]);
            ulonglong2 woA = *reinterpret_cast<const ulonglong2*>(&sm.sW2root[kk][opb]);
            ulonglong2 woB = *reinterpret_cast<const ulonglong2*>(&sm.sW2root[kk][opb + 2]);
#pragma unroll
            for (int n = 0; n < 8; n++) {
                unsigned long long a2 = *reinterpret_cast<const unsigned long long*>(&sm.sA2[ng + 16 * n][kk]);
                unsigned long long x2 = *reinterpret_cast<const unsigned long long*>(&sm.sX2[ng + 16 * n][kk]);
                FMA2(acc[n][0], a2, wrA.x);
                FMA2(acc[n][1], a2, wrA.y);
                FMA2(acc[n][2], a2, wrB.x);
                FMA2(acc[n][3], a2, wrB.y);
                FMA2(acc[n][0], x2, woA.x);
                FMA2(acc[n][1], x2, woA.y);
                FMA2(acc[n][2], x2, woB.x);
                FMA2(acc[n][3], x2, woB.y);
            }
        }
    }

    // ---- epilogue: bias + relu + store ----
    float4 b0 = *reinterpret_cast<const float4*>(&brel[og * 8]);
    float4 b1 = *reinterpret_cast<const float4*>(&brel[og * 8 + 4]);
#pragma unroll
    for (int n = 0; n < 8; n++) {
        int node = nodeBase + ng + 16 * n;
        if (node < N_NODES) {
            float r[8];
            UNPACK2(r[0], r[1], acc[n][0]);
            UNPACK2(r[2], r[3], acc[n][1]);
            UNPACK2(r[4], r[5], acc[n][2]);
            UNPACK2(r[6], r[7], acc[n][3]);
            float4 o0, o1;
            o0.x = fmaxf(r[0] + b0.x, 0.f);
            o0.y = fmaxf(r[1] + b0.y, 0.f);
            o0.z = fmaxf(r[2] + b0.z, 0.f);
            o0.w = fmaxf(r[3] + b0.w, 0.f);
            o1.x = fmaxf(r[4] + b1.x, 0.f);
            o1.y = fmaxf(r[5] + b1.y, 0.f);
            o1.z = fmaxf(r[6] + b1.z, 0.f);
            o1.w = fmaxf(r[7] + b1.w, 0.f);
            float4* orow = reinterpret_cast<float4*>(out) + node * 32;
            orow[og * 2]     = o0;
            orow[og * 2 + 1] = o1;
        }
    }
}

// ---------------------------------------------------------------------------
extern "C" void kernel_launch(void* const* d_in, const int* in_sizes, int n_in,
                              void* d_out, int out_size) {
    const float* x     = (const float*)d_in[0];
    const int*   ei    = (const int*)d_in[1];     // int32 (JAX x64 disabled)
    const float* Wrel  = (const float*)d_in[2];
    const float* brel  = (const float*)d_in[3];
    const float* Wroot = (const float*)d_in[4];
    float*       out   = (float*)d_out;

    const int E = in_sizes[1] / 2;                // 800000
    const int* src = ei;
    const int* dst = ei + E;

    const int smem_bytes = (int)sizeof(GemmSmem);     // ~99.6KB
    static bool attr_set = false;
    if (!attr_set) {
        cudaFuncSetAttribute(gemm_relu_kernel,
                             cudaFuncAttributeMaxDynamicSharedMemorySize,
                             smem_bytes);
        attr_set = true;
    }

    // 1) CSR build
    zero_deg_kernel<<<(N_NODES + 255) / 256, 256>>>();
    hist_kernel<<<(E + 255) / 256, 256>>>(dst, E);
    scan_kernel<<<1, 1024>>>();
    reorder_kernel<<<(E + 255) / 256, 256>>>(src, dst, E);

    // 2) aggregate: warp per node
    agg_kernel<<<(N_NODES * 32 + 255) / 256, 256>>>(
        reinterpret_cast<const float4*>(x));

    // 3) dual GEMM + bias + relu
    gemm_relu_kernel<<<(N_NODES + NPB - 1) / NPB, 256, smem_bytes>>>(
        x, Wrel, brel, Wroot, out);
}

// round 6
// speedup vs baseline: 1.7039x; 1.0421x over previous
#include <cuda_runtime.h>

#define N_NODES 50000
#define F       128
#define E_MAX   800000
#define NPB     64      // nodes per block in GEMM
#define KT      32      // weight k-tile

// ---- static device scratch (no allocs allowed) ----
__device__ int   g_deg[N_NODES];
__device__ int   g_off[N_NODES + 1];
__device__ int   g_cursor[N_NODES];
__device__ int   g_src_sorted[E_MAX];
__device__ float g_agg[N_NODES * F];

// ---- packed fp32x2 helpers (sm_100+; ptxas never auto-emits FFMA2) ----
#define FMA2(d, a, b) asm("fma.rn.f32x2 %0, %1, %2, %0;" : "+l"(d) : "l"(a), "l"(b))
#define PACK2(d, s)   asm("mov.b64 %0, {%1, %1};" : "=l"(d) : "f"(s))
#define UNPACK2(lo, hi, v) asm("mov.b64 {%0, %1}, %2;" : "=f"(lo), "=f"(hi) : "l"(v))

// ---------------------------------------------------------------------------
// CSR build: zero degrees -> histogram -> prefix scan -> reorder src by dst
// ---------------------------------------------------------------------------
__global__ void zero_deg_kernel() {
    int i = blockIdx.x * blockDim.x + threadIdx.x;
    if (i < N_NODES) g_deg[i] = 0;
}

__global__ void hist_kernel(const int* __restrict__ dst, int E) {
    int e = blockIdx.x * blockDim.x + threadIdx.x;
    if (e < E) atomicAdd(&g_deg[dst[e]], 1);
}

__global__ void __launch_bounds__(1024) scan_kernel() {
    __shared__ int wsum[32];
    __shared__ int carry;
    const int t = threadIdx.x, lane = t & 31, wid = t >> 5;
    if (t == 0) carry = 0;
    __syncthreads();
    for (int base = 0; base < N_NODES; base += 1024) {
        int i = base + t;
        int v = (i < N_NODES) ? g_deg[i] : 0;
        int inc = v;
#pragma unroll
        for (int d = 1; d < 32; d <<= 1) {
            int n = __shfl_up_sync(0xffffffffu, inc, d);
            if (lane >= d) inc += n;
        }
        if (lane == 31) wsum[wid] = inc;
        __syncthreads();
        if (wid == 0) {
            int ws = wsum[lane];
            int wi = ws;
#pragma unroll
            for (int d = 1; d < 32; d <<= 1) {
                int n = __shfl_up_sync(0xffffffffu, wi, d);
                if (lane >= d) wi += n;
            }
            wsum[lane] = wi - ws;
        }
        __syncthreads();
        int excl = carry + wsum[wid] + (inc - v);
        if (i < N_NODES) { g_off[i] = excl; g_cursor[i] = excl; }
        __syncthreads();
        if (t == 1023) carry = excl + v;
        __syncthreads();
    }
    if (t == 0) g_off[N_NODES] = carry;
}

__global__ void reorder_kernel(const int* __restrict__ src,
                               const int* __restrict__ dst, int E) {
    int e = blockIdx.x * blockDim.x + threadIdx.x;
    if (e < E) {
        int d = dst[e];
        int pos = atomicAdd(&g_cursor[d], 1);
        g_src_sorted[pos] = src[e];
    }
}

// ---------------------------------------------------------------------------
// Aggregate: one warp per node, neighbor loop unrolled x8 for MLP.
// ---------------------------------------------------------------------------
__global__ void __launch_bounds__(256)
agg_kernel(const float4* __restrict__ x4) {
    int node = (blockIdx.x * blockDim.x + threadIdx.x) >> 5;
    int lane = threadIdx.x & 31;
    if (node >= N_NODES) return;

    int beg = g_off[node];
    int end = g_off[node + 1];
    float4 acc = make_float4(0.f, 0.f, 0.f, 0.f);

    int i = beg;
    for (; i + 8 <= end; i += 8) {
        int s[8];
#pragma unroll
        for (int u = 0; u < 8; u++) s[u] = g_src_sorted[i + u];
        float4 v[8];
#pragma unroll
        for (int u = 0; u < 8; u++) v[u] = x4[s[u] * 32 + lane];
#pragma unroll
        for (int u = 0; u < 8; u++) {
            acc.x += v[u].x; acc.y += v[u].y;
            acc.z += v[u].z; acc.w += v[u].w;
        }
    }
    for (; i < end; i++) {
        int s = g_src_sorted[i];
        float4 v = x4[s * 32 + lane];
        acc.x += v.x; acc.y += v.y; acc.z += v.z; acc.w += v.w;
    }
    reinterpret_cast<float4*>(g_agg)[node * 32 + lane] = acc;
}

// ---------------------------------------------------------------------------
// Dual GEMM + bias + ReLU, FFMA2. 256 threads, 64 nodes/block, 3 blocks/SM.
// Thread tile: 8 outputs (og = t>>4, broadcast weights) x 4 nodes
// (ng = t&15, nodes ng+16n, padded rows -> conflict-free). Inputs stored
// scalar in smem; f32x2 operand packed in-loop (2 MOVs, alu pipe).
// ---------------------------------------------------------------------------
struct GemmSmem {
    float2 sW2rel [KT][64];    // [kk][o/2] = (W[2p][k], W[2p+1][k])  16KB
    float2 sW2root[KT][64];    //                                     16KB
    float  sA[NPB][KT + 1];    // [node][kk]                          8.25KB
    float  sX[NPB][KT + 1];    //                                     8.25KB
};

__global__ void __launch_bounds__(256, 3)
gemm_relu_kernel(const float* __restrict__ x,
                 const float* __restrict__ Wrel,
                 const float* __restrict__ brel,
                 const float* __restrict__ Wroot,
                 float* __restrict__ out) {
    extern __shared__ char smem_raw[];
    GemmSmem& sm = *reinterpret_cast<GemmSmem*>(smem_raw);

    const int t  = threadIdx.x;
    const int og = t >> 4;     // 0..15 -> output cols og*8..+7 (uniform/half-warp)
    const int ng = t & 15;     // nodes ng, ng+16, ng+32, ng+48
    const int nodeBase = blockIdx.x * NPB;

    unsigned long long acc[4][4];
#pragma unroll
    for (int n = 0; n < 4; n++)
#pragma unroll
        for (int p = 0; p < 4; p++) acc[n][p] = 0ull;

    for (int kc = 0; kc < F; kc += KT) {
        __syncthreads();

        // --- stage weights as adjacent-output pairs: sW2[kk][o/2]
        {
            int o  = t >> 1;            // 0..127
            int kq = (t & 1) * 16;      // 0 or 16
#pragma unroll
            for (int j = 0; j < 4; j++) {
                float4 wr = *reinterpret_cast<const float4*>(&Wrel [o * F + kc + kq + j * 4]);
                float4 wo = *reinterpret_cast<const float4*>(&Wroot[o * F + kc + kq + j * 4]);
                const float* wrp = reinterpret_cast<const float*>(&wr);
                const float* wop = reinterpret_cast<const float*>(&wo);
#pragma unroll
                for (int c = 0; c < 4; c++) {
                    reinterpret_cast<float*>(&sm.sW2rel [kq + j * 4 + c][o >> 1])[o & 1] = wrp[c];
                    reinterpret_cast<float*>(&sm.sW2root[kq + j * 4 + c][o >> 1])[o & 1] = wop[c];
                }
            }
        }
        // --- stage inputs: 64 nodes x 32 k, scalar stores into padded rows
        {
            int slot = t >> 2;          // 0..63
            int kq   = (t & 3) * 8;     // 0,8,16,24
            int node = nodeBase + slot;
            int gc   = node < N_NODES ? node : N_NODES - 1;
#pragma unroll
            for (int j = 0; j < 2; j++) {
                float4 a  = *reinterpret_cast<const float4*>(&g_agg[gc * F + kc + kq + j * 4]);
                float4 xx = *reinterpret_cast<const float4*>(&x    [gc * F + kc + kq + j * 4]);
                const float* ap = reinterpret_cast<const float*>(&a);
                const float* xp = reinterpret_cast<const float*>(&xx);
#pragma unroll
                for (int c = 0; c < 4; c++) {
                    sm.sA[slot][kq + j * 4 + c] = ap[c];
                    sm.sX[slot][kq + j * 4 + c] = xp[c];
                }
            }
        }
        __syncthreads();

        // --- compute: per kk: 4 broadcast LDS.128 (weights) + 8 cf LDS.32
        //     (inputs) + 16 ALU packs + 32 FFMA2 -> FMA-pipe bound
        const int opb = og * 4;
#pragma unroll
        for (int kk = 0; kk < KT; kk++) {
            ulonglong2 wrA = *reinterpret_cast<const ulonglong2*>(&sm.sW2rel [kk][opb]);
            ulonglong2 wrB = *reinterpret_cast<const ulonglong2*>(&sm.sW2rel [kk][opb + 2]);
            ulonglong2 woA = *reinterpret_cast<const ulonglong2*>(&sm.sW2root[kk][opb]);
            ulonglong2 woB = *reinterpret_cast<const ulonglong2*>(&sm.sW2root[kk][opb + 2]);
#pragma unroll
            for (int n = 0; n < 4; n++) {
                float a  = sm.sA[ng + 16 * n][kk];
                float xx = sm.sX[ng + 16 * n][kk];
                unsigned long long a2, x2;
                PACK2(a2, a);
                PACK2(x2, xx);
                FMA2(acc[n][0], a2, wrA.x);
                FMA2(acc[n][1], a2, wrA.y);
                FMA2(acc[n][2], a2, wrB.x);
                FMA2(acc[n][3], a2, wrB.y);
                FMA2(acc[n][0], x2, woA.x);
                FMA2(acc[n][1], x2, woA.y);
                FMA2(acc[n][2], x2, woB.x);
                FMA2(acc[n][3], x2, woB.y);
            }
        }
    }

    // ---- epilogue: bias + relu + store ----
    float4 b0 = *reinterpret_cast<const float4*>(&brel[og * 8]);
    float4 b1 = *reinterpret_cast<const float4*>(&brel[og * 8 + 4]);
#pragma unroll
    for (int n = 0; n < 4; n++) {
        int node = nodeBase + ng + 16 * n;
        if (node < N_NODES) {
            float r[8];
            UNPACK2(r[0], r[1], acc[n][0]);
            UNPACK2(r[2], r[3], acc[n][1]);
            UNPACK2(r[4], r[5], acc[n][2]);
            UNPACK2(r[6], r[7], acc[n][3]);
            float4 o0, o1;
            o0.x = fmaxf(r[0] + b0.x, 0.f);
            o0.y = fmaxf(r[1] + b0.y, 0.f);
            o0.z = fmaxf(r[2] + b0.z, 0.f);
            o0.w = fmaxf(r[3] + b0.w, 0.f);
            o1.x = fmaxf(r[4] + b1.x, 0.f);
            o1.y = fmaxf(r[5] + b1.y, 0.f);
            o1.z = fmaxf(r[6] + b1.z, 0.f);
            o1.w = fmaxf(r[7] + b1.w, 0.f);
            float4* orow = reinterpret_cast<float4*>(out) + node * 32;
            orow[og * 2]     = o0;
            orow[og * 2 + 1] = o1;
        }
    }
}

// ---------------------------------------------------------------------------
extern "C" void kernel_launch(void* const* d_in, const int* in_sizes, int n_in,
                              void* d_out, int out_size) {
    const float* x     = (const float*)d_in[0];
    const int*   ei    = (const int*)d_in[1];     // int32 (JAX x64 disabled)
    const float* Wrel  = (const float*)d_in[2];
    const float* brel  = (const float*)d_in[3];
    const float* Wroot = (const float*)d_in[4];
    float*       out   = (float*)d_out;

    const int E = in_sizes[1] / 2;                // 800000
    const int* src = ei;
    const int* dst = ei + E;

    const int smem_bytes = (int)sizeof(GemmSmem);     // ~48.9KB
    static bool attr_set = false;
    if (!attr_set) {
        cudaFuncSetAttribute(gemm_relu_kernel,
                             cudaFuncAttributeMaxDynamicSharedMemorySize,
                             smem_bytes);
        attr_set = true;
    }

    // 1) CSR build
    zero_deg_kernel<<<(N_NODES + 255) / 256, 256>>>();
    hist_kernel<<<(E + 255) / 256, 256>>>(dst, E);
    scan_kernel<<<1, 1024>>>();
    reorder_kernel<<<(E + 255) / 256, 256>>>(src, dst, E);

    // 2) aggregate: warp per node
    agg_kernel<<<(N_NODES * 32 + 255) / 256, 256>>>(
        reinterpret_cast<const float4*>(x));

    // 3) dual GEMM + bias + relu
    gemm_relu_kernel<<<(N_NODES + NPB - 1) / NPB, 256, smem_bytes>>>(
        x, Wrel, brel, Wroot, out);
}